// round 1
// baseline (speedup 1.0000x reference)
#include <cuda_runtime.h>

// Problem constants
#define BQ 16
#define KCH 64
#define HF 16
#define WF 16
#define HH 40
#define WW 80
#define LY 25
#define LX 65

// Tiling
#define NTQ 17           // x-quads: 17*4 = 68 >= 65 outputs
#define KC 8             // channels per chunk
#define NCHUNK 8         // 8 chunks * 8 = 64 channels
#define RS 84            // smem row stride (80 + 4 zero pad for window over-read)
#define CCS (HF*RS + 4)  // comp smem channel stride (=1348, +4 to break bank alignment)
#define PCS 260          // piece smem channel stride (256 + 4)
#define NWORK (NTQ*KC)   // 136 active compute threads
#define NTHREADS 160
#define GRID (BQ*LY + BQ)   // 400 2d CTAs + 16 1d CTAs

#define SMEM_FLOATS (KC*CCS + KC*PCS)   // 10784 + 2080 = 12864 floats = 51456 B

extern __shared__ float smem_raw[];

__global__ __launch_bounds__(NTHREADS) void corr_kernel(
    const float* __restrict__ piece,
    const float* __restrict__ comp,
    const float* __restrict__ strip,
    float* __restrict__ out)
{
    float* comp_s  = smem_raw;             // [KC][HF][RS] with channel stride CCS
    float* piece_s = smem_raw + KC*CCS;    // [KC][HF*WF] with channel stride PCS

    const int cta = blockIdx.x;
    const int tid = threadIdx.x;

    int b, y, srcH, kshift;
    const float* src;
    float* optr;
    if (cta < BQ*LY) {
        b = cta / LY; y = cta % LY;
        src = comp + (size_t)b * KCH * HH * WW;
        srcH = HH; kshift = 0;
        optr = out + (size_t)cta * LX;
    } else {
        b = cta - BQ*LY; y = 0;
        src = strip + (size_t)b * KCH * HF * WW;
        srcH = HF; kshift = KCH/2;   // piece_comp[k] = piece[(k+32)%64]
        optr = out + (size_t)BQ*LY*LX + (size_t)b * LX;
    }
    const float* pc = piece + (size_t)b * KCH * HF * WF;

    const int  ks = tid / NTQ;       // channel slice within chunk (0..7)
    const int  tq = tid % NTQ;       // x-quad index (0..16)
    const bool active = (tid < NWORK);
    const int  x0 = tq * 4;

    float acc0 = 0.f, acc1 = 0.f, acc2 = 0.f, acc3 = 0.f;

    for (int ch = 0; ch < NCHUNK; ch++) {
        __syncthreads();   // previous chunk's compute done before overwrite

        // ---- stage comp/strip chunk: KC channels x HF rows x 84 (80 data + 4 zero) ----
        for (int s = tid; s < KC * HF * 21; s += NTHREADS) {
            int c   = s / (HF*21);
            int rem = s - c * (HF*21);
            int r   = rem / 21;
            int q   = rem - r * 21;
            float4 v;
            if (q < 20)
                v = *(const float4*)(src + ((size_t)(ch*KC + c) * srcH + (y + r)) * WW + q*4);
            else
                v = make_float4(0.f, 0.f, 0.f, 0.f);
            *(float4*)(comp_s + c*CCS + r*RS + q*4) = v;
        }
        // ---- stage piece chunk (with channel roll for the 1d path) ----
        for (int s = tid; s < KC * 64; s += NTHREADS) {
            int c   = s / 64;
            int rem = s - c * 64;
            int cg  = (ch*KC + c + kshift) & (KCH - 1);
            float4 v = *(const float4*)(pc + (size_t)cg * HF * WF + rem*4);
            *(float4*)(piece_s + c*PCS + rem*4) = v;
        }
        __syncthreads();

        // ---- compute: this thread's channel = ks, outputs x0..x0+3 ----
        if (active) {
            const float* cb = comp_s  + ks*CCS;
            const float* pb = piece_s + ks*PCS;
            #pragma unroll 2
            for (int i = 0; i < HF; i++) {
                float w[20];
                const float* crow = cb + i*RS + x0;
                #pragma unroll
                for (int q = 0; q < 5; q++) {
                    float4 v = *(const float4*)(crow + q*4);
                    w[4*q+0] = v.x; w[4*q+1] = v.y; w[4*q+2] = v.z; w[4*q+3] = v.w;
                }
                float p[16];
                const float* prow = pb + i*WF;
                #pragma unroll
                for (int q = 0; q < 4; q++) {
                    float4 v = *(const float4*)(prow + q*4);
                    p[4*q+0] = v.x; p[4*q+1] = v.y; p[4*q+2] = v.z; p[4*q+3] = v.w;
                }
                #pragma unroll
                for (int j = 0; j < 16; j++) {
                    acc0 += p[j] * w[j+0];
                    acc1 += p[j] * w[j+1];
                    acc2 += p[j] * w[j+2];
                    acc3 += p[j] * w[j+3];
                }
            }
        }
    }

    // ---- cross-slice reduction (reuse comp smem region) ----
    __syncthreads();
    float* red = smem_raw;   // [KC][68]
    if (active) {
        red[ks*68 + x0 + 0] = acc0;
        red[ks*68 + x0 + 1] = acc1;
        red[ks*68 + x0 + 2] = acc2;
        red[ks*68 + x0 + 3] = acc3;
    }
    __syncthreads();
    if (tid < LX) {
        float s = 0.f;
        #pragma unroll
        for (int k2 = 0; k2 < KC; k2++) s += red[k2*68 + tid];
        optr[tid] = s;
    }
}

extern "C" void kernel_launch(void* const* d_in, const int* in_sizes, int n_in,
                              void* d_out, int out_size)
{
    const float* piece = (const float*)d_in[0];   // [16,64,16,16]
    const float* comp  = (const float*)d_in[1];   // [16,64,40,80]
    const float* strip = (const float*)d_in[2];   // [16,64,16,80]
    float* out = (float*)d_out;                   // [16*25*65] ++ [16*65]

    static bool attr_set = false;
    // setting the attribute is idempotent; do it unconditionally to stay
    // deterministic and capture-safe
    cudaFuncSetAttribute(corr_kernel,
                         cudaFuncAttributeMaxDynamicSharedMemorySize,
                         SMEM_FLOATS * (int)sizeof(float));
    (void)attr_set;

    corr_kernel<<<GRID, NTHREADS, SMEM_FLOATS * (int)sizeof(float)>>>(
        piece, comp, strip, out);
}

// round 3
// speedup vs baseline: 1.1795x; 1.1795x over previous
#include <cuda_runtime.h>

// Problem constants
#define BQ 16
#define KCH 64
#define HF 16
#define WF 16
#define HH 40
#define WW 80
#define LY 25
#define LX 65

// Tiling
#define NTQ 17           // x-quads: 17*4 = 68 >= 65 outputs
#define KC 8             // channels per chunk
#define NCHUNK 8         // 8 chunks * 8 = 64 channels
#define RS 84            // smem row stride (80 + 4 zero pad for window over-read)
#define CCS (HF*RS + 4)  // comp smem channel stride (=1348, +4 to skew banks)
#define PCS 260          // piece smem channel stride (256 + 4)
#define NWORK (NTQ*KC)   // 136 active compute threads
#define NTHREADS 160
#define GRID (BQ*LY + BQ)   // 400 2d CTAs + 16 1d CTAs

#define SMEM_FLOATS (KC*CCS + KC*PCS)   // 12864 floats = 51456 B

extern __shared__ float smem_raw[];

__global__ __launch_bounds__(NTHREADS, 4) void corr_kernel(
    const float* __restrict__ piece,
    const float* __restrict__ comp,
    const float* __restrict__ strip,
    float* __restrict__ out)
{
    float* comp_s  = smem_raw;             // [KC][HF][RS] with channel stride CCS
    float* piece_s = smem_raw + KC*CCS;    // [KC][HF*WF] with channel stride PCS

    const int cta = blockIdx.x;
    const int tid = threadIdx.x;

    int b, y, srcH, kshift;
    const float* src;
    float* optr;
    if (cta < BQ*LY) {
        b = cta / LY; y = cta % LY;
        src = comp + (size_t)b * KCH * HH * WW;
        srcH = HH; kshift = 0;
        optr = out + (size_t)cta * LX;
    } else {
        b = cta - BQ*LY; y = 0;
        src = strip + (size_t)b * KCH * HF * WW;
        srcH = HF; kshift = KCH/2;   // piece_comp[k] = piece[(k+32)%64]
        optr = out + (size_t)BQ*LY*LX + (size_t)b * LX;
    }
    const float* pc = piece + (size_t)b * KCH * HF * WF;

    const int  ks = tid / NTQ;       // channel slice within chunk (0..7)
    const int  tq = tid % NTQ;       // x-quad index (0..16)
    const bool active = (tid < NWORK);
    const int  x0 = tq * 4;

    float acc0 = 0.f, acc1 = 0.f, acc2 = 0.f, acc3 = 0.f;

    for (int ch = 0; ch < NCHUNK; ch++) {
        __syncthreads();   // previous chunk's compute done before overwrite

        // ---- stage comp/strip chunk: KC channels x HF rows x 84 (80 data + 4 zero) ----
        #pragma unroll 4
        for (int s = tid; s < KC * HF * 21; s += NTHREADS) {
            int c   = s / (HF*21);
            int rem = s - c * (HF*21);
            int r   = rem / 21;
            int q   = rem - r * 21;
            float4 v;
            if (q < 20)
                v = *(const float4*)(src + ((size_t)(ch*KC + c) * srcH + (y + r)) * WW + q*4);
            else
                v = make_float4(0.f, 0.f, 0.f, 0.f);
            *(float4*)(comp_s + c*CCS + r*RS + q*4) = v;
        }
        // ---- stage piece chunk (with channel roll for the 1d path) ----
        #pragma unroll 4
        for (int s = tid; s < KC * 64; s += NTHREADS) {
            int c   = s / 64;
            int rem = s - c * 64;
            int cg  = (ch*KC + c + kshift) & (KCH - 1);
            float4 v = *(const float4*)(pc + (size_t)cg * HF * WF + rem*4);
            *(float4*)(piece_s + c*PCS + rem*4) = v;
        }
        __syncthreads();

        // ---- compute: this thread's channel = ks, outputs x0..x0+3 ----
        // Fully unrolled straight-line body: lets ptxas hoist LDS.128s far
        // ahead of their consuming FFMAs (reg budget raised via launch_bounds).
        if (active) {
            const float* cb = comp_s  + ks*CCS + x0;
            const float* pb = piece_s + ks*PCS;
            #pragma unroll
            for (int i = 0; i < HF; i++) {
                const float* crow = cb + i*RS;
                const float* prow = pb + i*WF;
                float4 w0 = *(const float4*)(crow +  0);
                float4 w1 = *(const float4*)(crow +  4);
                float4 w2 = *(const float4*)(crow +  8);
                float4 w3 = *(const float4*)(crow + 12);
                float4 w4 = *(const float4*)(crow + 16);
                float4 p0 = *(const float4*)(prow +  0);
                float4 p1 = *(const float4*)(prow +  4);
                float4 p2 = *(const float4*)(prow +  8);
                float4 p3 = *(const float4*)(prow + 12);

                float w[20] = { w0.x,w0.y,w0.z,w0.w, w1.x,w1.y,w1.z,w1.w,
                                w2.x,w2.y,w2.z,w2.w, w3.x,w3.y,w3.z,w3.w,
                                w4.x,w4.y,w4.z,w4.w };
                float p[16] = { p0.x,p0.y,p0.z,p0.w, p1.x,p1.y,p1.z,p1.w,
                                p2.x,p2.y,p2.z,p2.w, p3.x,p3.y,p3.z,p3.w };
                #pragma unroll
                for (int j = 0; j < 16; j++) {
                    acc0 += p[j] * w[j+0];
                    acc1 += p[j] * w[j+1];
                    acc2 += p[j] * w[j+2];
                    acc3 += p[j] * w[j+3];
                }
            }
        }
    }

    // ---- cross-slice reduction (reuse comp smem region) ----
    __syncthreads();
    float* red = smem_raw;   // [KC][68]
    if (active) {
        red[ks*68 + x0 + 0] = acc0;
        red[ks*68 + x0 + 1] = acc1;
        red[ks*68 + x0 + 2] = acc2;
        red[ks*68 + x0 + 3] = acc3;
    }
    __syncthreads();
    if (tid < LX) {
        float s = 0.f;
        #pragma unroll
        for (int k2 = 0; k2 < KC; k2++) s += red[k2*68 + tid];
        optr[tid] = s;
    }
}

extern "C" void kernel_launch(void* const* d_in, const int* in_sizes, int n_in,
                              void* d_out, int out_size)
{
    const float* piece = (const float*)d_in[0];   // [16,64,16,16]
    const float* comp  = (const float*)d_in[1];   // [16,64,40,80]
    const float* strip = (const float*)d_in[2];   // [16,64,16,80]
    float* out = (float*)d_out;                   // [16*25*65] ++ [16*65]

    cudaFuncSetAttribute(corr_kernel,
                         cudaFuncAttributeMaxDynamicSharedMemorySize,
                         SMEM_FLOATS * (int)sizeof(float));

    corr_kernel<<<GRID, NTHREADS, SMEM_FLOATS * (int)sizeof(float)>>>(
        piece, comp, strip, out);
}

// round 4
// speedup vs baseline: 1.2710x; 1.0776x over previous
#include <cuda_runtime.h>

// Problem constants
#define BQ 16
#define KCH 64
#define HF 16
#define WF 16
#define HH 40
#define WW 80
#define LY 25
#define LX 65

// Tiling
#define NTQ 17           // x-quads: 17*4 = 68 >= 65 outputs
#define KC 8             // channels per chunk
#define NCHUNK 8         // 8 chunks * 8 = 64 channels
#define RS 84            // smem row stride (80 + 4 zero pad for window over-read)
#define CCS (HF*RS + 4)  // comp smem channel stride (=1348, +4 to skew banks)
#define PCS 260          // piece smem channel stride (256 + 4)
#define NWORK (2*KC*NTQ) // 272 active compute threads (2 row-halves x 8 ks x 17 tq)
#define NTHREADS 288     // 9 warps
#define GRID (BQ*LY + BQ)   // 400 2d CTAs + 16 1d CTAs

#define SMEM_FLOATS (KC*CCS + KC*PCS)   // 12864 floats = 51456 B

extern __shared__ float smem_raw[];

__global__ __launch_bounds__(NTHREADS, 3) void corr_kernel(
    const float* __restrict__ piece,
    const float* __restrict__ comp,
    const float* __restrict__ strip,
    float* __restrict__ out)
{
    float* comp_s  = smem_raw;             // [KC][HF][RS] with channel stride CCS
    float* piece_s = smem_raw + KC*CCS;    // [KC][HF*WF] with channel stride PCS

    const int cta = blockIdx.x;
    const int tid = threadIdx.x;

    int b, y, srcH, kshift;
    const float* src;
    float* optr;
    if (cta < BQ*LY) {
        b = cta / LY; y = cta % LY;
        src = comp + (size_t)b * KCH * HH * WW;
        srcH = HH; kshift = 0;
        optr = out + (size_t)cta * LX;
    } else {
        b = cta - BQ*LY; y = 0;
        src = strip + (size_t)b * KCH * HF * WW;
        srcH = HF; kshift = KCH/2;   // piece_comp[k] = piece[(k+32)%64]
        optr = out + (size_t)BQ*LY*LX + (size_t)b * LX;
    }
    const float* pc = piece + (size_t)b * KCH * HF * WF;

    // Compute-thread layout: half = row-half (rows 0-7 vs 8-15), ks = channel
    // slice within chunk, tq = x-quad.
    const int  half = tid / (KC*NTQ);        // 0 or 1 (tid<272)
    const int  rem  = tid - half*(KC*NTQ);
    const int  ks   = rem / NTQ;             // 0..7
    const int  tq   = rem - ks*NTQ;          // 0..16
    const bool active = (tid < NWORK);
    const int  x0 = tq * 4;
    const int  i0 = half * (HF/2);           // starting template row

    float acc0 = 0.f, acc1 = 0.f, acc2 = 0.f, acc3 = 0.f;

    for (int ch = 0; ch < NCHUNK; ch++) {
        __syncthreads();   // previous chunk's compute done before overwrite

        // ---- stage comp/strip chunk: KC channels x HF rows x 84 (80 data + 4 zero) ----
        #pragma unroll 4
        for (int s = tid; s < KC * HF * 21; s += NTHREADS) {
            int c   = s / (HF*21);
            int rem2 = s - c * (HF*21);
            int r   = rem2 / 21;
            int q   = rem2 - r * 21;
            float4 v;
            if (q < 20)
                v = *(const float4*)(src + ((size_t)(ch*KC + c) * srcH + (y + r)) * WW + q*4);
            else
                v = make_float4(0.f, 0.f, 0.f, 0.f);
            *(float4*)(comp_s + c*CCS + r*RS + q*4) = v;
        }
        // ---- stage piece chunk (with channel roll for the 1d path) ----
        #pragma unroll 2
        for (int s = tid; s < KC * 64; s += NTHREADS) {
            int c   = s / 64;
            int rem2 = s - c * 64;
            int cg  = (ch*KC + c + kshift) & (KCH - 1);
            float4 v = *(const float4*)(pc + (size_t)cg * HF * WF + rem2*4);
            *(float4*)(piece_s + c*PCS + rem2*4) = v;
        }
        __syncthreads();

        // ---- compute: channel = ks, template rows i0..i0+7, outputs x0..x0+3 ----
        if (active) {
            const float* cb = comp_s  + ks*CCS + x0 + i0*RS;
            const float* pb = piece_s + ks*PCS + i0*WF;
            #pragma unroll
            for (int i = 0; i < HF/2; i++) {
                const float* crow = cb + i*RS;
                const float* prow = pb + i*WF;
                float4 w0 = *(const float4*)(crow +  0);
                float4 w1 = *(const float4*)(crow +  4);
                float4 w2 = *(const float4*)(crow +  8);
                float4 w3 = *(const float4*)(crow + 12);
                float4 w4 = *(const float4*)(crow + 16);
                float4 p0 = *(const float4*)(prow +  0);
                float4 p1 = *(const float4*)(prow +  4);
                float4 p2 = *(const float4*)(prow +  8);
                float4 p3 = *(const float4*)(prow + 12);

                float w[20] = { w0.x,w0.y,w0.z,w0.w, w1.x,w1.y,w1.z,w1.w,
                                w2.x,w2.y,w2.z,w2.w, w3.x,w3.y,w3.z,w3.w,
                                w4.x,w4.y,w4.z,w4.w };
                float p[16] = { p0.x,p0.y,p0.z,p0.w, p1.x,p1.y,p1.z,p1.w,
                                p2.x,p2.y,p2.z,p2.w, p3.x,p3.y,p3.z,p3.w };
                #pragma unroll
                for (int j = 0; j < 16; j++) {
                    acc0 += p[j] * w[j+0];
                    acc1 += p[j] * w[j+1];
                    acc2 += p[j] * w[j+2];
                    acc3 += p[j] * w[j+3];
                }
            }
        }
    }

    // ---- cross-slice reduction: 16 partials (2 halves x 8 ks) per x ----
    __syncthreads();
    float* red = smem_raw;   // [16][68]
    if (active) {
        int slot = half * KC + ks;
        red[slot*68 + x0 + 0] = acc0;
        red[slot*68 + x0 + 1] = acc1;
        red[slot*68 + x0 + 2] = acc2;
        red[slot*68 + x0 + 3] = acc3;
    }
    __syncthreads();
    if (tid < LX) {
        float s = 0.f;
        #pragma unroll
        for (int k2 = 0; k2 < 2*KC; k2++) s += red[k2*68 + tid];
        optr[tid] = s;
    }
}

extern "C" void kernel_launch(void* const* d_in, const int* in_sizes, int n_in,
                              void* d_out, int out_size)
{
    const float* piece = (const float*)d_in[0];   // [16,64,16,16]
    const float* comp  = (const float*)d_in[1];   // [16,64,40,80]
    const float* strip = (const float*)d_in[2];   // [16,64,16,80]
    float* out = (float*)d_out;                   // [16*25*65] ++ [16*65]

    cudaFuncSetAttribute(corr_kernel,
                         cudaFuncAttributeMaxDynamicSharedMemorySize,
                         SMEM_FLOATS * (int)sizeof(float));

    corr_kernel<<<GRID, NTHREADS, SMEM_FLOATS * (int)sizeof(float)>>>(
        piece, comp, strip, out);
}

// round 5
// speedup vs baseline: 1.3794x; 1.0853x over previous
#include <cuda_runtime.h>

// Problem constants
#define BQ 16
#define KCH 64
#define HF 16
#define WF 16
#define HH 40
#define WW 80
#define LY 25
#define LX 65

// Tiling
#define NTQ 17           // x-quads: 17*4 = 68 >= 65 outputs
#define KC 8             // channels per chunk
#define NCHUNK 8         // 8 chunks * 8 = 64 channels
#define RS 84            // smem row stride (80 + 4 zero pad for window over-read)
#define CCS (HF*RS + 4)  // comp smem channel stride (=1348; mod 32 == 4 bank skew)
#define PCS 260          // piece smem channel stride (256 + 4)
#define NWORK (2*KC*NTQ) // 272 active compute threads (2 row-halves x 8 ks x 17 tq)
#define NTHREADS 288     // 9 warps
#define GRID (BQ*LY + BQ)   // 400 2d CTAs + 16 1d CTAs

#define SMEM_FLOATS (KC*CCS + KC*PCS)   // 12864 floats = 51456 B

extern __shared__ float smem_raw[];

__global__ __launch_bounds__(NTHREADS, 3) void corr_kernel(
    const float* __restrict__ piece,
    const float* __restrict__ comp,
    const float* __restrict__ strip,
    float* __restrict__ out)
{
    float* comp_s  = smem_raw;             // [KC][HF][RS] with channel stride CCS
    float* piece_s = smem_raw + KC*CCS;    // [KC][HF*WF] with channel stride PCS

    const int cta = blockIdx.x;
    const int tid = threadIdx.x;

    int b, y, srcH, kshift;
    const float* src;
    float* optr;
    if (cta < BQ*LY) {
        b = cta / LY; y = cta % LY;
        src = comp + (size_t)b * KCH * HH * WW;
        srcH = HH; kshift = 0;
        optr = out + (size_t)cta * LX;
    } else {
        b = cta - BQ*LY; y = 0;
        src = strip + (size_t)b * KCH * HF * WW;
        srcH = HF; kshift = KCH/2;   // piece_comp[k] = piece[(k+32)%64]
        optr = out + (size_t)BQ*LY*LX + (size_t)b * LX;
    }
    const float* pc = piece + (size_t)b * KCH * HF * WF;

    // ---- staging thread map (computed once; no div/mod in the hot loops) ----
    // comp: 24 q-slots (21 used) x 12 row-slots; rows advance by 12/pass.
    const int q24 = tid % 24;          // quad slot 0..23 (21 used: 20 data + 1 pad)
    const int r12 = tid / 24;          // row slot 0..11
    const bool q_data = (q24 < 20);
    const bool q_pad  = (q24 == 20);

    // Compute-thread layout: half = row-half (rows 0-7 vs 8-15), ks = channel
    // slice within chunk, tq = x-quad.
    const int  half = tid / (KC*NTQ);        // 0 or 1 (tid<272)
    const int  rem  = tid - half*(KC*NTQ);
    const int  ks   = rem / NTQ;             // 0..7
    const int  tq   = rem - ks*NTQ;          // 0..16
    const bool active = (tid < NWORK);
    const int  x0 = tq * 4;
    const int  i0 = half * (HF/2);           // starting template row

    float acc0 = 0.f, acc1 = 0.f, acc2 = 0.f, acc3 = 0.f;

    for (int ch = 0; ch < NCHUNK; ch++) {
        __syncthreads();   // previous chunk's compute done before overwrite

        // ---- stage comp/strip chunk: KC*HF = 128 channel-rows x 21 quads ----
        // row index r in [0,128): c = r>>4 (channel in chunk), rr = r&15 (row)
        #pragma unroll
        for (int pass = 0; pass < 11; pass++) {
            int r = r12 + pass * 12;
            if (r < KC*HF) {
                int c  = r >> 4;
                int rr = r & 15;
                if (q_data) {
                    float4 v = *(const float4*)(src +
                        ((size_t)(ch*KC + c) * srcH + (y + rr)) * WW + q24*4);
                    *(float4*)(comp_s + c*CCS + rr*RS + q24*4) = v;
                } else if (q_pad) {
                    *(float4*)(comp_s + c*CCS + rr*RS + 80) =
                        make_float4(0.f, 0.f, 0.f, 0.f);
                }
            }
        }
        // ---- stage piece chunk: 512 float4s (pow-2 index math) ----
        #pragma unroll
        for (int pass = 0; pass < 2; pass++) {
            int s = tid + pass * NTHREADS;
            if (s < KC * 64) {
                int c    = s >> 6;
                int rem2 = s & 63;
                int cg   = (ch*KC + c + kshift) & (KCH - 1);
                float4 v = *(const float4*)(pc + (size_t)cg * (HF*WF) + rem2*4);
                *(float4*)(piece_s + c*PCS + rem2*4) = v;
            }
        }
        __syncthreads();

        // ---- compute: channel = ks, template rows i0..i0+7, outputs x0..x0+3 ----
        if (active) {
            const float* cb = comp_s  + ks*CCS + x0 + i0*RS;
            const float* pb = piece_s + ks*PCS + i0*WF;
            #pragma unroll
            for (int i = 0; i < HF/2; i++) {
                const float* crow = cb + i*RS;
                const float* prow = pb + i*WF;
                // Load DIRECTLY into the register arrays — no element copies.
                float w[20];
                *(float4*)(w +  0) = *(const float4*)(crow +  0);
                *(float4*)(w +  4) = *(const float4*)(crow +  4);
                *(float4*)(w +  8) = *(const float4*)(crow +  8);
                *(float4*)(w + 12) = *(const float4*)(crow + 12);
                *(float4*)(w + 16) = *(const float4*)(crow + 16);
                float p[16];
                *(float4*)(p +  0) = *(const float4*)(prow +  0);
                *(float4*)(p +  4) = *(const float4*)(prow +  4);
                *(float4*)(p +  8) = *(const float4*)(prow +  8);
                *(float4*)(p + 12) = *(const float4*)(prow + 12);
                #pragma unroll
                for (int j = 0; j < 16; j++) {
                    acc0 += p[j] * w[j+0];
                    acc1 += p[j] * w[j+1];
                    acc2 += p[j] * w[j+2];
                    acc3 += p[j] * w[j+3];
                }
            }
        }
    }

    // ---- cross-slice reduction: 16 partials (2 halves x 8 ks) per x ----
    __syncthreads();
    float* red = smem_raw;   // [16][68]
    if (active) {
        int slot = half * KC + ks;
        red[slot*68 + x0 + 0] = acc0;
        red[slot*68 + x0 + 1] = acc1;
        red[slot*68 + x0 + 2] = acc2;
        red[slot*68 + x0 + 3] = acc3;
    }
    __syncthreads();
    if (tid < LX) {
        float s = 0.f;
        #pragma unroll
        for (int k2 = 0; k2 < 2*KC; k2++) s += red[k2*68 + tid];
        optr[tid] = s;
    }
}

extern "C" void kernel_launch(void* const* d_in, const int* in_sizes, int n_in,
                              void* d_out, int out_size)
{
    const float* piece = (const float*)d_in[0];   // [16,64,16,16]
    const float* comp  = (const float*)d_in[1];   // [16,64,40,80]
    const float* strip = (const float*)d_in[2];   // [16,64,16,80]
    float* out = (float*)d_out;                   // [16*25*65] ++ [16*65]

    cudaFuncSetAttribute(corr_kernel,
                         cudaFuncAttributeMaxDynamicSharedMemorySize,
                         SMEM_FLOATS * (int)sizeof(float));

    corr_kernel<<<GRID, NTHREADS, SMEM_FLOATS * (int)sizeof(float)>>>(
        piece, comp, strip, out);
}

// round 6
// speedup vs baseline: 1.4434x; 1.0463x over previous
#include <cuda_runtime.h>

// Problem constants
#define BQ 16
#define KCH 64
#define HF 16
#define WF 16
#define HH 40
#define WW 80
#define LY 25
#define LX 65

// Tiling
#define NTO 9            // x-octs: 9*8 = 72 >= 65 outputs
#define KC 8             // channels per chunk
#define NCHUNK 8         // 8 chunks * 8 = 64 channels
#define RS 88            // smem row stride (80 data + 8 zero pad for 24-wide window)
#define CCS (HF*RS + 4)  // comp smem channel stride (=1412; mod 32 == 4 bank skew)
#define PCS 260          // piece smem channel stride (256 + 4; mod 32 == 4)
#define NTHREADS 288     // 9 warps; 4 quarters x 8 ks x 9 to = 288, all active
#define GRID (BQ*LY + BQ)   // 400 2d CTAs + 16 1d CTAs

#define SMEM_FLOATS (KC*CCS + KC*PCS)   // 11296 + 2080 = 13376 floats = 53504 B

extern __shared__ float smem_raw[];

__global__ __launch_bounds__(NTHREADS, 3) void corr_kernel(
    const float* __restrict__ piece,
    const float* __restrict__ comp,
    const float* __restrict__ strip,
    float* __restrict__ out)
{
    float* comp_s  = smem_raw;             // [KC][HF][RS] channel stride CCS
    float* piece_s = smem_raw + KC*CCS;    // [KC][HF*WF] channel stride PCS

    const int cta = blockIdx.x;
    const int tid = threadIdx.x;

    int b, y, srcH, kshift;
    const float* src;
    float* optr;
    if (cta < BQ*LY) {
        b = cta / LY; y = cta % LY;
        src = comp + (size_t)b * KCH * HH * WW;
        srcH = HH; kshift = 0;
        optr = out + (size_t)cta * LX;
    } else {
        b = cta - BQ*LY; y = 0;
        src = strip + (size_t)b * KCH * HF * WW;
        srcH = HF; kshift = KCH/2;   // piece_comp[k] = piece[(k+32)%64]
        optr = out + (size_t)BQ*LY*LX + (size_t)b * LX;
    }
    const float* pc = piece + (size_t)b * KCH * HF * WF;

    // ---- staging thread map (no div/mod in hot loops) ----
    // comp rows: 24 q-slots (20 data + 2 zero-pad quads) x 12 row-slots
    const int q24 = tid % 24;
    const int r12 = tid / 24;
    const bool q_data = (q24 < 20);
    const bool q_pad  = (q24 >= 20 && q24 < 22);   // pads words 80..87

    // Compute layout: quarter (4 template rows each) x ks x x-oct
    const int quarter = tid / 72;            // 0..3
    const int rem     = tid - quarter*72;
    const int ks      = rem / NTO;           // 0..7
    const int to      = rem - ks*NTO;        // 0..8
    const int x0      = to * 8;
    const int i0      = quarter * (HF/4);    // starting template row

    float acc[8];
    #pragma unroll
    for (int t = 0; t < 8; t++) acc[t] = 0.f;

    for (int ch = 0; ch < NCHUNK; ch++) {
        __syncthreads();   // previous chunk's compute done before overwrite

        // ---- stage comp/strip chunk: 128 channel-rows x (20 data + 2 pad) quads ----
        #pragma unroll
        for (int pass = 0; pass < 11; pass++) {
            int r = r12 + pass * 12;
            if (r < KC*HF) {
                int c  = r >> 4;
                int rr = r & 15;
                if (q_data) {
                    float4 v = *(const float4*)(src +
                        ((size_t)(ch*KC + c) * srcH + (y + rr)) * WW + q24*4);
                    *(float4*)(comp_s + c*CCS + rr*RS + q24*4) = v;
                } else if (q_pad) {
                    *(float4*)(comp_s + c*CCS + rr*RS + q24*4) =
                        make_float4(0.f, 0.f, 0.f, 0.f);
                }
            }
        }
        // ---- stage piece chunk: 512 float4s (pow-2 index math) ----
        #pragma unroll
        for (int pass = 0; pass < 2; pass++) {
            int s = tid + pass * NTHREADS;
            if (s < KC * 64) {
                int c    = s >> 6;
                int rem2 = s & 63;
                int cg   = (ch*KC + c + kshift) & (KCH - 1);
                float4 v = *(const float4*)(pc + (size_t)cg * (HF*WF) + rem2*4);
                *(float4*)(piece_s + c*PCS + rem2*4) = v;
            }
        }
        __syncthreads();

        // ---- compute: channel ks, rows i0..i0+3, outputs x0..x0+7 ----
        {
            const float* cb = comp_s  + ks*CCS + x0 + i0*RS;
            const float* pb = piece_s + ks*PCS + i0*WF;
            #pragma unroll
            for (int i = 0; i < HF/4; i++) {
                const float* crow = cb + i*RS;
                const float* prow = pb + i*WF;
                float w[24];
                *(float4*)(w +  0) = *(const float4*)(crow +  0);
                *(float4*)(w +  4) = *(const float4*)(crow +  4);
                *(float4*)(w +  8) = *(const float4*)(crow +  8);
                *(float4*)(w + 12) = *(const float4*)(crow + 12);
                *(float4*)(w + 16) = *(const float4*)(crow + 16);
                *(float4*)(w + 20) = *(const float4*)(crow + 20);
                float p[16];
                *(float4*)(p +  0) = *(const float4*)(prow +  0);
                *(float4*)(p +  4) = *(const float4*)(prow +  4);
                *(float4*)(p +  8) = *(const float4*)(prow +  8);
                *(float4*)(p + 12) = *(const float4*)(prow + 12);
                #pragma unroll
                for (int j = 0; j < 16; j++) {
                    #pragma unroll
                    for (int t = 0; t < 8; t++)
                        acc[t] += p[j] * w[j+t];
                }
            }
        }
    }

    // ---- cross-slice reduction: 32 partials (4 quarters x 8 ks) per x ----
    __syncthreads();
    float* red = smem_raw;   // [32][72]
    {
        int slot = quarter * KC + ks;
        *(float4*)(red + slot*72 + x0 + 0) = make_float4(acc[0],acc[1],acc[2],acc[3]);
        *(float4*)(red + slot*72 + x0 + 4) = make_float4(acc[4],acc[5],acc[6],acc[7]);
    }
    __syncthreads();
    if (tid < LX) {
        float s = 0.f;
        #pragma unroll
        for (int k2 = 0; k2 < 32; k2++) s += red[k2*72 + tid];
        optr[tid] = s;
    }
}

extern "C" void kernel_launch(void* const* d_in, const int* in_sizes, int n_in,
                              void* d_out, int out_size)
{
    const float* piece = (const float*)d_in[0];   // [16,64,16,16]
    const float* comp  = (const float*)d_in[1];   // [16,64,40,80]
    const float* strip = (const float*)d_in[2];   // [16,64,16,80]
    float* out = (float*)d_out;                   // [16*25*65] ++ [16*65]

    cudaFuncSetAttribute(corr_kernel,
                         cudaFuncAttributeMaxDynamicSharedMemorySize,
                         SMEM_FLOATS * (int)sizeof(float));

    corr_kernel<<<GRID, NTHREADS, SMEM_FLOATS * (int)sizeof(float)>>>(
        piece, comp, strip, out);
}

// round 8
// speedup vs baseline: 1.5153x; 1.0498x over previous
#include <cuda_runtime.h>

// Problem constants
#define BQ 16
#define KCH 64
#define HF 16
#define WF 16
#define HH 40
#define WW 80
#define LY 25
#define LX 65

// Tiling: 5 x-tiles of 16 outputs (80 >= 65), 8 ks, 8 row-pairs
#define NTILE 5
#define KC 8
#define NCHUNK 8
#define RS 96            // comp row stride (words): 80 data + 16 zero pad; mult of 4
#define CCS (HF*RS + 4)  // 1540: ≡ 0 mod 4 (align), ≡ 4 mod 32 (conflict-free lanes)
#define PRS 16           // piece row stride (natural, aligned)
#define PCS (HF*PRS + 4) // 260: ≡ 0 mod 4, ≡ 4 mod 32
#define NTHREADS 320     // 10 warps, all active
#define GRID (BQ*LY + BQ)

#define SMEM_FLOATS (KC*CCS + KC*PCS)   // 12320 + 2080 = 14400 floats = 57600 B

extern __shared__ float smem_raw[];

__global__ __launch_bounds__(NTHREADS, 3) void corr_kernel(
    const float* __restrict__ piece,
    const float* __restrict__ comp,
    const float* __restrict__ strip,
    float* __restrict__ out)
{
    float* comp_s  = smem_raw;             // [KC][HF][RS] channel stride CCS
    float* piece_s = smem_raw + KC*CCS;    // [KC][HF][PRS] channel stride PCS

    const int cta = blockIdx.x;
    const int tid = threadIdx.x;

    int b, y, srcH, kshift;
    const float* src;
    float* optr;
    if (cta < BQ*LY) {
        b = cta / LY; y = cta % LY;
        src = comp + (size_t)b * KCH * HH * WW;
        srcH = HH; kshift = 0;
        optr = out + (size_t)cta * LX;
    } else {
        b = cta - BQ*LY; y = 0;
        src = strip + (size_t)b * KCH * HF * WW;
        srcH = HF; kshift = KCH/2;   // piece_comp[k] = piece[(k+32)%64]
        optr = out + (size_t)BQ*LY*LX + (size_t)b * LX;
    }
    const float* pc = piece + (size_t)b * KCH * HF * WF;

    // Compute layout: ks FASTEST lane index. Adjacent lanes differ by CCS
    // (or PCS) words; CCS*4 ≡ 16 mod 128 -> the 8 lanes of each LDS phase
    // hit 8 distinct 16B bank groups -> conflict-free, and all offsets are
    // multiples of 16B -> aligned.
    const int tile = tid / 64;           // 0..4
    const int rem  = tid - tile*64;
    const int rp   = rem >> 3;           // 0..7 row-pair
    const int ks   = rem & 7;            // 0..7 channel slice (lane-fastest)
    const int x0   = tile * 16;
    const int i0   = rp * 2;

    float acc[16];
    #pragma unroll
    for (int t = 0; t < 16; t++) acc[t] = 0.f;

    for (int ch = 0; ch < NCHUNK; ch++) {
        __syncthreads();

        // ---- stage comp/strip chunk: 128 channel-rows x 24 quads ----
        // quads 0..19 = data, 20..23 = zero pad (words 80..95)
        for (int s = tid; s < KC*HF*24; s += NTHREADS) {
            int rowidx = s / 24;
            int q      = s - rowidx*24;
            int c  = rowidx >> 4;
            int rr = rowidx & 15;
            float4 v;
            if (q < 20)
                v = *(const float4*)(src +
                    ((size_t)(ch*KC + c) * srcH + (y + rr)) * WW + q*4);
            else
                v = make_float4(0.f, 0.f, 0.f, 0.f);
            *(float4*)(comp_s + c*CCS + rr*RS + q*4) = v;
        }
        // ---- stage piece chunk: KC channels x 16 rows x 4 quads ----
        for (int s = tid; s < KC*HF*4; s += NTHREADS) {
            int c4  = s & 3;
            int row = (s >> 2) & 15;
            int c   = s >> 6;
            int cg  = (ch*KC + c + kshift) & (KCH - 1);
            float4 v = *(const float4*)(pc + (size_t)cg * (HF*WF) + row*WF + c4*4);
            *(float4*)(piece_s + c*PCS + row*PRS + c4*4) = v;
        }
        __syncthreads();

        // ---- compute: channel ks, rows i0,i0+1, outputs x0..x0+15 ----
        {
            const float* cb = comp_s  + ks*CCS + i0*RS + x0;
            const float* pb = piece_s + ks*PCS + i0*PRS;
            #pragma unroll
            for (int r2 = 0; r2 < 2; r2++) {
                const float* crow = cb + r2*RS;
                const float* prow = pb + r2*PRS;
                // First half: j=0..7 needs w[0..22], p[0..7]
                float w[32];
                float p[16];
                *(float4*)(w +  0) = *(const float4*)(crow +  0);
                *(float4*)(w +  4) = *(const float4*)(crow +  4);
                *(float4*)(w +  8) = *(const float4*)(crow +  8);
                *(float4*)(w + 12) = *(const float4*)(crow + 12);
                *(float4*)(w + 16) = *(const float4*)(crow + 16);
                *(float4*)(w + 20) = *(const float4*)(crow + 20);
                *(float4*)(p +  0) = *(const float4*)(prow +  0);
                *(float4*)(p +  4) = *(const float4*)(prow +  4);
                #pragma unroll
                for (int j = 0; j < 8; j++) {
                    #pragma unroll
                    for (int t = 0; t < 16; t++)
                        acc[t] += p[j] * w[j+t];
                }
                // Second half: j=8..15 needs w[8..31], p[8..15]
                // (w[0..7] now dead -> register reuse)
                *(float4*)(w + 24) = *(const float4*)(crow + 24);
                *(float4*)(w + 28) = *(const float4*)(crow + 28);
                *(float4*)(p +  8) = *(const float4*)(prow +  8);
                *(float4*)(p + 12) = *(const float4*)(prow + 12);
                #pragma unroll
                for (int j = 8; j < 16; j++) {
                    #pragma unroll
                    for (int t = 0; t < 16; t++)
                        acc[t] += p[j] * w[j+t];
                }
            }
        }
    }

    // ---- cross-slice reduction: 64 partials (8 rp x 8 ks) per x, stride 84 ----
    __syncthreads();
    float* red = smem_raw;   // [64][84]
    {
        int slot = rp * KC + ks;
        float* rb = red + slot*84 + x0;
        *(float4*)(rb +  0) = make_float4(acc[ 0],acc[ 1],acc[ 2],acc[ 3]);
        *(float4*)(rb +  4) = make_float4(acc[ 4],acc[ 5],acc[ 6],acc[ 7]);
        *(float4*)(rb +  8) = make_float4(acc[ 8],acc[ 9],acc[10],acc[11]);
        *(float4*)(rb + 12) = make_float4(acc[12],acc[13],acc[14],acc[15]);
    }
    __syncthreads();
    if (tid < LX) {
        float s = 0.f;
        #pragma unroll
        for (int k2 = 0; k2 < 64; k2++) s += red[k2*84 + tid];
        optr[tid] = s;
    }
}

extern "C" void kernel_launch(void* const* d_in, const int* in_sizes, int n_in,
                              void* d_out, int out_size)
{
    const float* piece = (const float*)d_in[0];   // [16,64,16,16]
    const float* comp  = (const float*)d_in[1];   // [16,64,40,80]
    const float* strip = (const float*)d_in[2];   // [16,64,16,80]
    float* out = (float*)d_out;                   // [16*25*65] ++ [16*65]

    cudaFuncSetAttribute(corr_kernel,
                         cudaFuncAttributeMaxDynamicSharedMemorySize,
                         SMEM_FLOATS * (int)sizeof(float));

    corr_kernel<<<GRID, NTHREADS, SMEM_FLOATS * (int)sizeof(float)>>>(
        piece, comp, strip, out);
}

// round 10
// speedup vs baseline: 2.0265x; 1.3373x over previous
#include <cuda_runtime.h>

// Problem constants
#define BQ 16
#define KCH 64
#define HF 16
#define WF 16
#define HH 40
#define WW 80
#define LY 25
#define LX 65

// Tiling: 5 x-tiles of 16 outputs (80 >= 65), 8 ks, 8 row-pairs
#define KC 8
#define NCHUNK 8
#define RS 96            // comp row stride (words): 80 data + 16 zero pad
#define CCS (HF*RS + 4)  // 1540: mult of 4 (align), ≡4 mod 32 (conflict-free lanes)
#define PRS 16           // piece row stride
#define PCS (HF*PRS + 4) // 260: mult of 4, ≡4 mod 32
#define NTHREADS 320     // 10 warps, all active
#define GRID (BQ*LY + BQ)

#define SMEM_FLOATS (KC*CCS + KC*PCS)   // 14400 floats = 57600 B

extern __shared__ float smem_raw[];

__global__ __launch_bounds__(NTHREADS, 3) void corr_kernel(
    const float* __restrict__ piece,
    const float* __restrict__ comp,
    const float* __restrict__ strip,
    float* __restrict__ out)
{
    float* comp_s  = smem_raw;             // [KC][HF][RS] channel stride CCS
    float* piece_s = smem_raw + KC*CCS;    // [KC][HF][PRS] channel stride PCS

    const int cta = blockIdx.x;
    const int tid = threadIdx.x;

    int b, y, srcH, kshift;
    const float* src;
    float* optr;
    if (cta < BQ*LY) {
        b = cta / LY; y = cta % LY;
        src = comp + (size_t)b * KCH * HH * WW;
        srcH = HH; kshift = 0;
        optr = out + (size_t)cta * LX;
    } else {
        b = cta - BQ*LY; y = 0;
        src = strip + (size_t)b * KCH * HF * WW;
        srcH = HF; kshift = KCH/2;   // piece_comp[k] = piece[(k+32)%64]
        optr = out + (size_t)BQ*LY*LX + (size_t)b * LX;
    }
    const float* pc = piece + (size_t)b * KCH * HF * WF;

    // Div-free staging map: 320 = 20 quads x 16 rows exactly.
    const int q20 = tid % 20;       // data quad 0..19
    const int r16 = tid / 20;       // row 0..15

    // Compute layout: ks fastest -> lanes differ by CCS/PCS (≡16B mod 128B)
    // -> conflict-free aligned LDS.128.
    const int tile = tid / 64;           // 0..4
    const int rem  = tid - tile*64;
    const int rp   = rem >> 3;           // 0..7 row-pair
    const int ks   = rem & 7;            // 0..7 channel slice (lane-fastest)
    const int x0   = tile * 16;
    const int i0   = rp * 2;

    // ---- one-time zero padding: words 80..95 of all 128 channel-rows ----
    // (never overwritten by data stores, valid for every chunk)
    #pragma unroll
    for (int pass = 0; pass < 2; pass++) {
        int s = tid + pass * NTHREADS;
        if (s < KC*HF*4) {
            int c    = s >> 6;
            int rr   = (s >> 2) & 15;
            int quad = s & 3;
            *(float4*)(comp_s + c*CCS + rr*RS + 80 + quad*4) =
                make_float4(0.f, 0.f, 0.f, 0.f);
        }
    }

    float acc[16];
    #pragma unroll
    for (int t = 0; t < 16; t++) acc[t] = 0.f;

    for (int ch = 0; ch < NCHUNK; ch++) {
        __syncthreads();

        // ---- stage comp/strip data: 8 passes, c = pass, row = r16, quad = q20 ----
        #pragma unroll
        for (int pass = 0; pass < KC; pass++) {
            float4 v = *(const float4*)(src +
                ((size_t)(ch*KC + pass) * srcH + (y + r16)) * WW + q20*4);
            *(float4*)(comp_s + pass*CCS + r16*RS + q20*4) = v;
        }
        // ---- stage piece chunk: 512 float4s (pow-2 index math) ----
        #pragma unroll
        for (int pass = 0; pass < 2; pass++) {
            int s = tid + pass * NTHREADS;
            if (s < KC*HF*4) {
                int c4  = s & 3;
                int row = (s >> 2) & 15;
                int c   = s >> 6;
                int cg  = (ch*KC + c + kshift) & (KCH - 1);
                float4 v = *(const float4*)(pc + (size_t)cg*(HF*WF) + row*WF + c4*4);
                *(float4*)(piece_s + c*PCS + row*PRS + c4*4) = v;
            }
        }
        __syncthreads();

        // ---- compute: channel ks, rows i0,i0+1, outputs x0..x0+15 ----
        {
            const float* cb = comp_s  + ks*CCS + i0*RS + x0;
            const float* pb = piece_s + ks*PCS + i0*PRS;
            #pragma unroll
            for (int r2 = 0; r2 < 2; r2++) {
                const float* crow = cb + r2*RS;
                const float* prow = pb + r2*PRS;
                // JIT quad loading keeps live window at w[20]+p[4]+acc[16].
                float w[32];
                float p[16];
                *(float4*)(w +  0) = *(const float4*)(crow +  0);
                *(float4*)(w +  4) = *(const float4*)(crow +  4);
                *(float4*)(w +  8) = *(const float4*)(crow +  8);
                *(float4*)(w + 12) = *(const float4*)(crow + 12);
                *(float4*)(p +  0) = *(const float4*)(prow +  0);
                #pragma unroll
                for (int jb = 0; jb < 4; jb++) {
                    // next window quad (w[16+4jb .. 19+4jb])
                    *(float4*)(w + 16 + 4*jb) = *(const float4*)(crow + 16 + 4*jb);
                    if (jb > 0)  // next piece quad
                        *(float4*)(p + 4*jb) = *(const float4*)(prow + 4*jb);
                    #pragma unroll
                    for (int j = 4*jb; j < 4*jb + 4; j++) {
                        #pragma unroll
                        for (int t = 0; t < 16; t++)
                            acc[t] += p[j] * w[j+t];
                    }
                }
            }
        }
    }

    // ---- cross-slice reduction: 64 partials (8 rp x 8 ks) per x, stride 84 ----
    __syncthreads();
    float* red = smem_raw;   // [64][84]
    {
        int slot = rp * KC + ks;
        float* rb = red + slot*84 + x0;
        *(float4*)(rb +  0) = make_float4(acc[ 0],acc[ 1],acc[ 2],acc[ 3]);
        *(float4*)(rb +  4) = make_float4(acc[ 4],acc[ 5],acc[ 6],acc[ 7]);
        *(float4*)(rb +  8) = make_float4(acc[ 8],acc[ 9],acc[10],acc[11]);
        *(float4*)(rb + 12) = make_float4(acc[12],acc[13],acc[14],acc[15]);
    }
    __syncthreads();
    if (tid < LX) {
        float s = 0.f;
        #pragma unroll
        for (int k2 = 0; k2 < 64; k2++) s += red[k2*84 + tid];
        optr[tid] = s;
    }
}

extern "C" void kernel_launch(void* const* d_in, const int* in_sizes, int n_in,
                              void* d_out, int out_size)
{
    const float* piece = (const float*)d_in[0];   // [16,64,16,16]
    const float* comp  = (const float*)d_in[1];   // [16,64,40,80]
    const float* strip = (const float*)d_in[2];   // [16,64,16,80]
    float* out = (float*)d_out;                   // [16*25*65] ++ [16*65]

    cudaFuncSetAttribute(corr_kernel,
                         cudaFuncAttributeMaxDynamicSharedMemorySize,
                         SMEM_FLOATS * (int)sizeof(float));

    corr_kernel<<<GRID, NTHREADS, SMEM_FLOATS * (int)sizeof(float)>>>(
        piece, comp, strip, out);
}

// round 11
// speedup vs baseline: 2.0413x; 1.0073x over previous
#include <cuda_runtime.h>

// Problem constants
#define BQ 16
#define KCH 64
#define HF 16
#define WF 16
#define HH 40
#define WW 80
#define LY 25
#define LX 65

// Tiling: 5 x-tiles of 16 outputs (80 >= 65), 8 ks, 8 row-pairs
#define KC 8
#define NCHUNK 8
#define RS 96            // comp row stride (words): 80 data + 16 zero pad
#define CCS (HF*RS + 4)  // 1540: mult of 4 (align), ≡4 mod 32 (conflict-free lanes)
#define PRS 16           // piece row stride
#define PCS (HF*PRS + 4) // 260: mult of 4, ≡4 mod 32
#define NTHREADS 320     // 10 warps, all active
#define GRID (BQ*LY + BQ)

#define SMEM_FLOATS (KC*CCS + KC*PCS)   // 14400 floats = 57600 B

extern __shared__ float smem_raw[];

// ---- packed f32x2 helpers (Blackwell FFMA2 path; exact fp32 semantics) ----
__device__ __forceinline__ unsigned long long pk2(float lo, float hi) {
    unsigned long long r;
    asm("mov.b64 %0, {%1,%2};" : "=l"(r) : "f"(lo), "f"(hi));
    return r;
}
__device__ __forceinline__ void ffma2(unsigned long long& d,
                                      unsigned long long a,
                                      unsigned long long b) {
    asm("fma.rn.f32x2 %0, %1, %2, %0;" : "+l"(d) : "l"(a), "l"(b));
}
__device__ __forceinline__ float2 unpk2(unsigned long long v) {
    float2 f;
    asm("mov.b64 {%0,%1}, %2;" : "=f"(f.x), "=f"(f.y) : "l"(v));
    return f;
}

__global__ __launch_bounds__(NTHREADS, 3) void corr_kernel(
    const float* __restrict__ piece,
    const float* __restrict__ comp,
    const float* __restrict__ strip,
    float* __restrict__ out)
{
    float* comp_s  = smem_raw;             // [KC][HF][RS] channel stride CCS
    float* piece_s = smem_raw + KC*CCS;    // [KC][HF][PRS] channel stride PCS

    const int cta = blockIdx.x;
    const int tid = threadIdx.x;

    int b, y, srcH, kshift;
    const float* src;
    float* optr;
    if (cta < BQ*LY) {
        b = cta / LY; y = cta % LY;
        src = comp + (size_t)b * KCH * HH * WW;
        srcH = HH; kshift = 0;
        optr = out + (size_t)cta * LX;
    } else {
        b = cta - BQ*LY; y = 0;
        src = strip + (size_t)b * KCH * HF * WW;
        srcH = HF; kshift = KCH/2;   // piece_comp[k] = piece[(k+32)%64]
        optr = out + (size_t)BQ*LY*LX + (size_t)b * LX;
    }
    const float* pc = piece + (size_t)b * KCH * HF * WF;

    // Div-free staging map: 320 = 20 quads x 16 rows exactly.
    const int q20 = tid % 20;       // data quad 0..19
    const int r16 = tid / 20;       // row 0..15

    // Compute layout: ks fastest -> per quarter-warp phase the 8 lanes differ
    // by CCS/PCS (≡16B mod 128B) -> conflict-free aligned LDS.128.
    const int tile = tid / 64;           // 0..4
    const int rem  = tid - tile*64;
    const int rp   = rem >> 3;           // 0..7 row-pair
    const int ks   = rem & 7;            // 0..7 channel slice (lane-fastest)
    const int x0   = tile * 16;
    const int i0   = rp * 2;

    // ---- one-time zero padding: words 80..95 of all 128 channel-rows ----
    #pragma unroll
    for (int pass = 0; pass < 2; pass++) {
        int s = tid + pass * NTHREADS;
        if (s < KC*HF*4) {
            int c    = s >> 6;
            int rr   = (s >> 2) & 15;
            int quad = s & 3;
            *(float4*)(comp_s + c*CCS + rr*RS + 80 + quad*4) =
                make_float4(0.f, 0.f, 0.f, 0.f);
        }
    }

    // Packed accumulators: accE[tt]=(t=2tt,2tt+1) fed by even j;
    // accO[tt]=(t=2tt+1,2tt+2) fed by odd j (t=16 half discarded);
    // accS = scalar t=0 contribution from odd j.
    unsigned long long accE[8], accO[8];
    float accS = 0.f;
    #pragma unroll
    for (int t = 0; t < 8; t++) { accE[t] = 0ull; accO[t] = 0ull; }

    for (int ch = 0; ch < NCHUNK; ch++) {
        __syncthreads();

        // ---- stage comp/strip data: 8 passes, c = pass, row = r16, quad = q20 ----
        #pragma unroll
        for (int pass = 0; pass < KC; pass++) {
            float4 v = *(const float4*)(src +
                ((size_t)(ch*KC + pass) * srcH + (y + r16)) * WW + q20*4);
            *(float4*)(comp_s + pass*CCS + r16*RS + q20*4) = v;
        }
        // ---- stage piece chunk: 512 float4s (pow-2 index math) ----
        #pragma unroll
        for (int pass = 0; pass < 2; pass++) {
            int s = tid + pass * NTHREADS;
            if (s < KC*HF*4) {
                int c4  = s & 3;
                int row = (s >> 2) & 15;
                int c   = s >> 6;
                int cg  = (ch*KC + c + kshift) & (KCH - 1);
                float4 v = *(const float4*)(pc + (size_t)cg*(HF*WF) + row*WF + c4*4);
                *(float4*)(piece_s + c*PCS + row*PRS + c4*4) = v;
            }
        }
        __syncthreads();

        // ---- compute: channel ks, rows i0,i0+1, outputs x0..x0+15 ----
        {
            const float* cb = comp_s  + ks*CCS + i0*RS + x0;
            const float* pb = piece_s + ks*PCS + i0*PRS;
            #pragma unroll
            for (int r2 = 0; r2 < 2; r2++) {
                const float* crow = cb + r2*RS;
                const float* prow = pb + r2*PRS;
                unsigned long long wp[16];   // even-offset pairs (w[2k],w[2k+1])
                // preload quads 0..4 -> wp[0..9]
                #pragma unroll
                for (int q = 0; q < 5; q++) {
                    float4 v = *(const float4*)(crow + 4*q);
                    wp[2*q]   = pk2(v.x, v.y);
                    wp[2*q+1] = pk2(v.z, v.w);
                }
                #pragma unroll
                for (int jb = 0; jb < 4; jb++) {
                    if (jb > 0) {            // JIT: quad jb+4 -> wp[2jb+8..9]
                        float4 v = *(const float4*)(crow + 4*(jb+4));
                        wp[2*jb+8] = pk2(v.x, v.y);
                        wp[2*jb+9] = pk2(v.z, v.w);
                    }
                    float4 pv = *(const float4*)(prow + 4*jb);
                    float pj[4] = {pv.x, pv.y, pv.z, pv.w};
                    #pragma unroll
                    for (int jj = 0; jj < 4; jj++) {
                        const int j = 4*jb + jj;
                        unsigned long long pd = pk2(pj[jj], pj[jj]);
                        if ((j & 1) == 0) {
                            #pragma unroll
                            for (int tt = 0; tt < 8; tt++)
                                ffma2(accE[tt], pd, wp[j/2 + tt]);
                        } else {
                            float2 wl = unpk2(wp[(j-1)/2]);
                            accS += pj[jj] * wl.y;       // t=0, w[j]
                            #pragma unroll
                            for (int tt = 0; tt < 8; tt++)
                                ffma2(accO[tt], pd, wp[(j+1)/2 + tt]);
                        }
                    }
                }
            }
        }
    }

    // ---- fold packed banks into 16 scalars ----
    float accf[16];
    #pragma unroll
    for (int tt = 0; tt < 8; tt++) {
        float2 e = unpk2(accE[tt]);
        accf[2*tt]   = e.x;
        accf[2*tt+1] = e.y;
    }
    accf[0] += accS;
    #pragma unroll
    for (int k = 0; k < 8; k++) {
        float2 o = unpk2(accO[k]);
        accf[2*k+1] += o.x;
        if (2*k+2 < 16) accf[2*k+2] += o.y;   // k=7 hi half = dummy t16
    }

    // ---- cross-slice reduction: 64 partials (8 rp x 8 ks) per x, stride 84 ----
    __syncthreads();
    float* red = smem_raw;   // [64][84]
    {
        int slot = rp * KC + ks;
        float* rb = red + slot*84 + x0;
        *(float4*)(rb +  0) = make_float4(accf[ 0],accf[ 1],accf[ 2],accf[ 3]);
        *(float4*)(rb +  4) = make_float4(accf[ 4],accf[ 5],accf[ 6],accf[ 7]);
        *(float4*)(rb +  8) = make_float4(accf[ 8],accf[ 9],accf[10],accf[11]);
        *(float4*)(rb + 12) = make_float4(accf[12],accf[13],accf[14],accf[15]);
    }
    __syncthreads();
    if (tid < LX) {
        float s = 0.f;
        #pragma unroll
        for (int k2 = 0; k2 < 64; k2++) s += red[k2*84 + tid];
        optr[tid] = s;
    }
}

extern "C" void kernel_launch(void* const* d_in, const int* in_sizes, int n_in,
                              void* d_out, int out_size)
{
    const float* piece = (const float*)d_in[0];   // [16,64,16,16]
    const float* comp  = (const float*)d_in[1];   // [16,64,40,80]
    const float* strip = (const float*)d_in[2];   // [16,64,16,80]
    float* out = (float*)d_out;                   // [16*25*65] ++ [16*65]

    cudaFuncSetAttribute(corr_kernel,
                         cudaFuncAttributeMaxDynamicSharedMemorySize,
                         SMEM_FLOATS * (int)sizeof(float));

    corr_kernel<<<GRID, NTHREADS, SMEM_FLOATS * (int)sizeof(float)>>>(
        piece, comp, strip, out);
}

// round 12
// speedup vs baseline: 2.0748x; 1.0164x over previous
#include <cuda_runtime.h>

// Problem constants
#define BQ 16
#define KCH 64
#define HF 16
#define WF 16
#define HH 40
#define WW 80
#define LY 25
#define LX 65

// Tiling: 5 x-tiles of 16 outputs (80 >= 65), 8 ks, 8 row-pairs
#define KC 8
#define NCHUNK 8
#define RS 96            // comp row stride (words): 80 data + 16 zero pad
#define CCS (HF*RS + 4)  // 1540: mult of 4 (align), ≡4 mod 32 (conflict-free lanes)
#define PRS 16           // piece row stride
#define PCS (HF*PRS + 4) // 260: mult of 4, ≡4 mod 32
#define NTHREADS 320     // 10 warps, all active
#define GRID (BQ*LY + BQ)

#define SMEM_FLOATS (KC*CCS + KC*PCS)   // 14400 floats = 57600 B

extern __shared__ float smem_raw[];

// ---- packed f32x2 helpers (Blackwell FFMA2 path; exact fp32 semantics) ----
__device__ __forceinline__ unsigned long long pk2(float lo, float hi) {
    unsigned long long r;
    asm("mov.b64 %0, {%1,%2};" : "=l"(r) : "f"(lo), "f"(hi));
    return r;
}
__device__ __forceinline__ void ffma2(unsigned long long& d,
                                      unsigned long long a,
                                      unsigned long long b) {
    asm("fma.rn.f32x2 %0, %1, %2, %0;" : "+l"(d) : "l"(a), "l"(b));
}
__device__ __forceinline__ float2 unpk2(unsigned long long v) {
    float2 f;
    asm("mov.b64 {%0,%1}, %2;" : "=f"(f.x), "=f"(f.y) : "l"(v));
    return f;
}

// ---- cp.async helpers ----
__device__ __forceinline__ unsigned smem_addr(const void* p) {
    return (unsigned)__cvta_generic_to_shared(p);
}
#define CP_ASYNC16(dst_u32, src) \
    asm volatile("cp.async.ca.shared.global [%0], [%1], 16;" \
                 :: "r"(dst_u32), "l"(src))
#define CP_COMMIT_WAIT() do { \
    asm volatile("cp.async.commit_group;"); \
    asm volatile("cp.async.wait_group 0;" ::: "memory"); \
} while (0)

__global__ __launch_bounds__(NTHREADS, 3) void corr_kernel(
    const float* __restrict__ piece,
    const float* __restrict__ comp,
    const float* __restrict__ strip,
    float* __restrict__ out)
{
    float* comp_s  = smem_raw;             // [KC][HF][RS] channel stride CCS
    float* piece_s = smem_raw + KC*CCS;    // [KC][HF][PRS] channel stride PCS
    const unsigned comp_u32  = smem_addr(comp_s);
    const unsigned piece_u32 = smem_addr(piece_s);

    const int cta = blockIdx.x;
    const int tid = threadIdx.x;

    int b, y, srcH, kshift;
    const float* src;
    float* optr;
    if (cta < BQ*LY) {
        b = cta / LY; y = cta % LY;
        src = comp + (size_t)b * KCH * HH * WW;
        srcH = HH; kshift = 0;
        optr = out + (size_t)cta * LX;
    } else {
        b = cta - BQ*LY; y = 0;
        src = strip + (size_t)b * KCH * HF * WW;
        srcH = HF; kshift = KCH/2;   // piece_comp[k] = piece[(k+32)%64]
        optr = out + (size_t)BQ*LY*LX + (size_t)b * LX;
    }
    const float* pc = piece + (size_t)b * KCH * HF * WF;

    // Div-free staging map: 320 = 20 quads x 16 rows exactly.
    const int q20 = tid % 20;       // data quad 0..19
    const int r16 = tid / 20;       // row 0..15

    // Compute layout: ks fastest -> 8 lanes/phase differ by CCS/PCS
    // (≡16B mod 128B) -> conflict-free aligned LDS.128.
    const int tile = tid / 64;           // 0..4
    const int rem  = tid - tile*64;
    const int rp   = rem >> 3;           // 0..7 row-pair
    const int ks   = rem & 7;            // 0..7 channel slice (lane-fastest)
    const int x0   = tile * 16;
    const int i0   = rp * 2;

    // ---- one-time zero padding: words 80..95 of all 128 channel-rows ----
    #pragma unroll
    for (int pass = 0; pass < 2; pass++) {
        int s = tid + pass * NTHREADS;
        if (s < KC*HF*4) {
            int c    = s >> 6;
            int rr   = (s >> 2) & 15;
            int quad = s & 3;
            *(float4*)(comp_s + c*CCS + rr*RS + 80 + quad*4) =
                make_float4(0.f, 0.f, 0.f, 0.f);
        }
    }

    // Packed accumulators: accE[tt]=(t=2tt,2tt+1) even j; accO[tt]=(t=2tt+1,
    // 2tt+2) odd j (t16 half discarded); accS = scalar t=0 odd-j term.
    unsigned long long accE[8], accO[8];
    float accS = 0.f;
    #pragma unroll
    for (int t = 0; t < 8; t++) { accE[t] = 0ull; accO[t] = 0ull; }

    const float* src_row = src + (size_t)(y + r16) * WW + q20*4;
    const unsigned comp_dst = comp_u32 + (unsigned)(r16*RS + q20*4) * 4u;

    for (int ch = 0; ch < NCHUNK; ch++) {
        __syncthreads();

        // ---- stage comp/strip data via cp.async: 8 channels/chunk ----
        #pragma unroll
        for (int pass = 0; pass < KC; pass++) {
            CP_ASYNC16(comp_dst + (unsigned)(pass*CCS)*4u,
                       src_row + (size_t)(ch*KC + pass) * srcH * WW);
        }
        // ---- stage piece chunk via cp.async: 512 float4s ----
        #pragma unroll
        for (int pass = 0; pass < 2; pass++) {
            int s = tid + pass * NTHREADS;
            if (s < KC*HF*4) {
                int c4  = s & 3;
                int row = (s >> 2) & 15;
                int c   = s >> 6;
                int cg  = (ch*KC + c + kshift) & (KCH - 1);
                CP_ASYNC16(piece_u32 + (unsigned)(c*PCS + row*PRS + c4*4)*4u,
                           pc + (size_t)cg*(HF*WF) + (s & 63)*4);
            }
        }
        CP_COMMIT_WAIT();
        __syncthreads();

        // ---- compute: channel ks, rows i0,i0+1, outputs x0..x0+15 ----
        {
            const float* cb = comp_s  + ks*CCS + i0*RS + x0;
            const float* pb = piece_s + ks*PCS + i0*PRS;
            #pragma unroll
            for (int r2 = 0; r2 < 2; r2++) {
                const float* crow = cb + r2*RS;
                const float* prow = pb + r2*PRS;
                unsigned long long wp[16];   // even-offset pairs (w[2k],w[2k+1])
                float p[16];
                #pragma unroll
                for (int q = 0; q < 5; q++) {       // preload quads 0..4
                    float4 v = *(const float4*)(crow + 4*q);
                    wp[2*q]   = pk2(v.x, v.y);
                    wp[2*q+1] = pk2(v.z, v.w);
                }
                *(float4*)(p + 0) = *(const float4*)(prow);
                #pragma unroll
                for (int jb = 0; jb < 4; jb++) {
                    if (jb < 3) {   // prefetch 1 full block ahead
                        float4 v = *(const float4*)(crow + 4*(jb+5));
                        wp[2*jb+10] = pk2(v.x, v.y);
                        wp[2*jb+11] = pk2(v.z, v.w);
                        *(float4*)(p + 4*(jb+1)) = *(const float4*)(prow + 4*(jb+1));
                    }
                    #pragma unroll
                    for (int jj = 0; jj < 4; jj++) {
                        const int j = 4*jb + jj;
                        const float pj = p[j];
                        unsigned long long pd = pk2(pj, pj);
                        if ((j & 1) == 0) {
                            #pragma unroll
                            for (int tt = 0; tt < 8; tt++)
                                ffma2(accE[tt], pd, wp[j/2 + tt]);
                        } else {
                            float2 wl = unpk2(wp[(j-1)/2]);
                            accS += pj * wl.y;       // t=0, w[j]
                            #pragma unroll
                            for (int tt = 0; tt < 8; tt++)
                                ffma2(accO[tt], pd, wp[(j+1)/2 + tt]);
                        }
                    }
                }
            }
        }
    }

    // ---- fold packed banks into 16 scalars ----
    float accf[16];
    #pragma unroll
    for (int tt = 0; tt < 8; tt++) {
        float2 e = unpk2(accE[tt]);
        accf[2*tt]   = e.x;
        accf[2*tt+1] = e.y;
    }
    accf[0] += accS;
    #pragma unroll
    for (int k = 0; k < 8; k++) {
        float2 o = unpk2(accO[k]);
        accf[2*k+1] += o.x;
        if (2*k+2 < 16) accf[2*k+2] += o.y;   // k=7 hi half = dummy t16
    }

    // ---- cross-slice reduction: 64 partials (8 rp x 8 ks) per x ----
    __syncthreads();
    float* red  = smem_raw;            // [64][84]
    float* part = smem_raw + 64*84;    // [4][68]
    {
        int slot = rp * KC + ks;
        float* rb = red + slot*84 + x0;
        *(float4*)(rb +  0) = make_float4(accf[ 0],accf[ 1],accf[ 2],accf[ 3]);
        *(float4*)(rb +  4) = make_float4(accf[ 4],accf[ 5],accf[ 6],accf[ 7]);
        *(float4*)(rb +  8) = make_float4(accf[ 8],accf[ 9],accf[10],accf[11]);
        *(float4*)(rb + 12) = make_float4(accf[12],accf[13],accf[14],accf[15]);
    }
    __syncthreads();
    if (tid < 4*LX) {                  // stage 1: 4 groups of 16 slots
        int g = tid / LX;
        int x = tid - g*LX;
        float s = 0.f;
        #pragma unroll
        for (int k2 = 0; k2 < 16; k2++) s += red[(g*16 + k2)*84 + x];
        part[g*68 + x] = s;
    }
    __syncthreads();
    if (tid < LX) {                    // stage 2: fold 4 partials
        optr[tid] = part[tid] + part[68 + tid] + part[136 + tid] + part[204 + tid];
    }
}

extern "C" void kernel_launch(void* const* d_in, const int* in_sizes, int n_in,
                              void* d_out, int out_size)
{
    const float* piece = (const float*)d_in[0];   // [16,64,16,16]
    const float* comp  = (const float*)d_in[1];   // [16,64,40,80]
    const float* strip = (const float*)d_in[2];   // [16,64,16,80]
    float* out = (float*)d_out;                   // [16*25*65] ++ [16*65]

    cudaFuncSetAttribute(corr_kernel,
                         cudaFuncAttributeMaxDynamicSharedMemorySize,
                         SMEM_FLOATS * (int)sizeof(float));

    corr_kernel<<<GRID, NTHREADS, SMEM_FLOATS * (int)sizeof(float)>>>(
        piece, comp, strip, out);
}